// round 9
// baseline (speedup 1.0000x reference)
#include <cuda_runtime.h>
#include <cstdint>
#include <cstddef>
#include <math.h>

#define LVL   3
#define BSZ   128
#define T0    256
#define STOCH 128
#define DETER 1024
#define EMBED 512
#define OBS_D 512
#define G3    (3*DETER)   // 3072
#define NB    128          // persistent grid (<=148 SMs, all co-resident)

typedef unsigned long long u64;

// ---------------------------------------------------------------------------
// Static device scratch (no allocations allowed).
// ---------------------------------------------------------------------------
__device__ float g_h[BSZ * EMBED];
__device__ float g_qh[BSZ * EMBED];
__device__ float g_dets1[BSZ * 64 * DETER];     // level-1 dets
__device__ float g_dets2[BSZ * 16 * DETER];     // level-2 dets
__device__ float g_pre_ctx[BSZ * 64 * EMBED];   // ctx @ Wp_ctx
__device__ float g_pre_obs[BSZ * T0 * EMBED];   // obs @ Wq_obs
__device__ float g_Wcomb[EMBED * EMBED];        // Wqm @ Wp_sample (per level)
__device__ float g_bvec[EMBED];                 // bp + bqm @ Wp_sample
// Duplicated ({w,w} pairs), chunk-tiled weights laid out in smem-consumption order.
__device__ __align__(16) float g_Wih_t[512 * 3072 * 2];
__device__ __align__(16) float g_Whh_t[1024 * 3072 * 2];
__device__ __align__(16) float g_Wq_t [1024 * 512 * 2];
__device__ __align__(16) float g_Wcomb_t[512 * 512 * 2];
__device__ unsigned int g_bar_count;
__device__ unsigned int g_bar_gen;

// ---------------------------------------------------------------------------
// Packed fp32 FMA (bit-exact fp32; only reachable via PTX) + cp.async helpers
// ---------------------------------------------------------------------------
__device__ __forceinline__ void ffma2(u64& d, u64 a, u64 b) {
    asm("fma.rn.f32x2 %0, %1, %2, %0;" : "+l"(d) : "l"(a), "l"(b));
}
__device__ __forceinline__ float2 unpack2(u64 v) {
    float lo, hi;
    asm("mov.b64 {%0, %1}, %2;" : "=f"(lo), "=f"(hi) : "l"(v));
    return make_float2(lo, hi);
}
__device__ __forceinline__ void cp16(float* s, const float* g) {
    unsigned a = (unsigned)__cvta_generic_to_shared(s);
    asm volatile("cp.async.cg.shared.global [%0], [%1], 16;" :: "r"(a), "l"(g));
}
__device__ __forceinline__ void cp_commit() { asm volatile("cp.async.commit_group;"); }
__device__ __forceinline__ void cp_wait0()  { asm volatile("cp.async.wait_group 0;"); }

// ---------------------------------------------------------------------------
// Software grid barrier. NB blocks all co-resident.
// ---------------------------------------------------------------------------
__device__ __forceinline__ void grid_sync() {
    __syncthreads();
    if (threadIdx.x == 0) {
        volatile unsigned int* genp = &g_bar_gen;
        unsigned int g = *genp;
        __threadfence();
        unsigned int a = atomicAdd(&g_bar_count, 1u);
        if (a == NB - 1u) {
            atomicExch(&g_bar_count, 0u);
            __threadfence();
            atomicAdd(&g_bar_gen, 1u);
        } else {
            while (*genp == g) { }
        }
        __threadfence();
    }
    __syncthreads();
}

// ---------------------------------------------------------------------------
// Precompute GEMM: C[M,N] = A[M,K] @ W[K,N]
// ---------------------------------------------------------------------------
__global__ __launch_bounds__(128) void gemm64_kernel(
    const float* __restrict__ A, int lda,
    const float* __restrict__ W, int ldw,
    float* __restrict__ C, int ldc, int K)
{
    constexpr int BM = 64, BN = 64, BK = 16, TM = 4, TN = 8;
    __shared__ float sA[BK][BM + 4];
    __shared__ float sW[BK][BN];

    const int tid  = threadIdx.x;
    const int tx   = tid & 7;
    const int ty   = tid >> 3;
    const int row0 = blockIdx.y * BM;
    const int col0 = blockIdx.x * BN;

    float acc[TM][TN];
    #pragma unroll
    for (int i = 0; i < TM; i++)
        #pragma unroll
        for (int j = 0; j < TN; j++) acc[i][j] = 0.0f;

    for (int k0 = 0; k0 < K; k0 += BK) {
        #pragma unroll
        for (int p = 0; p < 8; p++) {
            int i  = tid + p * 128;
            int kk = i & 15, r = i >> 4;
            sA[kk][r] = A[(size_t)(row0 + r) * lda + (k0 + kk)];
        }
        #pragma unroll
        for (int p = 0; p < 8; p++) {
            int i  = tid + p * 128;
            int kk = i >> 6, cc = i & 63;
            sW[kk][cc] = W[(size_t)(k0 + kk) * ldw + (col0 + cc)];
        }
        __syncthreads();
        #pragma unroll
        for (int kk = 0; kk < BK; kk++) {
            float4 av = *(const float4*)&sA[kk][ty * TM];
            float4 w0 = *(const float4*)&sW[kk][tx * TN];
            float4 w1 = *(const float4*)&sW[kk][tx * TN + 4];
            float a[TM] = {av.x, av.y, av.z, av.w};
            float w[TN] = {w0.x, w0.y, w0.z, w0.w, w1.x, w1.y, w1.z, w1.w};
            #pragma unroll
            for (int i = 0; i < TM; i++)
                #pragma unroll
                for (int j = 0; j < TN; j++)
                    acc[i][j] = fmaf(a[i], w[j], acc[i][j]);
        }
        __syncthreads();
    }

    #pragma unroll
    for (int i = 0; i < TM; i++) {
        int m  = row0 + ty * TM + i;
        int n0 = col0 + tx * TN;
        float4 o0 = {acc[i][0], acc[i][1], acc[i][2], acc[i][3]};
        float4 o1 = {acc[i][4], acc[i][5], acc[i][6], acc[i][7]};
        *(float4*)&C[(size_t)m * ldc + n0]     = o0;
        *(float4*)&C[(size_t)m * ldc + n0 + 4] = o1;
    }
}

// bvec[n] = bp[n] + sum_s bqm[s] * Wp_sample[s, n]
__global__ void bvec_kernel(const float* __restrict__ Wp,
                            const float* __restrict__ bp,
                            const float* __restrict__ bqm)
{
    const int n = blockIdx.x * blockDim.x + threadIdx.x;
    if (n >= EMBED) return;
    float s = bp[n];
    for (int k = 0; k < STOCH; k++)
        s = fmaf(bqm[k], Wp[(size_t)k * EMBED + n], s);
    g_bvec[n] = s;
}

// ---------------------------------------------------------------------------
// Weight dup + chunk-tiling pass.
// src: W[K][nseg*segN] row-major. dst pair index
//   o = (((jt*(K/32)+ch)*32+kk)*nseg + seg)*32 + c, value W[ch*32+kk][seg*segN + jt*32 + c]
// stored as {w,w} at dst[2o], dst[2o+1]. Chunk (jt,ch) = 32*nseg*64 contiguous floats
// = exactly the smem tile image -> cp.async-able byte-for-byte.
// ---------------------------------------------------------------------------
__global__ void dup_tile_kernel(const float* __restrict__ src,
                                float* __restrict__ dst,
                                int K, int nseg, int segN)
{
    const int total = K * nseg * segN;   // pair count
    const int kch = K / 32;
    for (int o = blockIdx.x * blockDim.x + threadIdx.x; o < total;
         o += gridDim.x * blockDim.x) {
        int c   = o & 31;
        int r   = o >> 5;
        int seg = r % nseg;       r /= nseg;
        int kk  = r & 31;         r >>= 5;
        int ch  = r % kch;
        int jt  = r / kch;
        float v = src[(size_t)(ch * 32 + kk) * (nseg * segN) + seg * segN + jt * 32 + c];
        float2 w = make_float2(v, v);
        *(float2*)&dst[(size_t)o * 2] = w;
    }
}

// ---------------------------------------------------------------------------
// Scan-kernel GEMM helpers. sA: [2][32][34] floats; sW: [2][6144] floats.
// ---------------------------------------------------------------------------

// 16m x 32n projection, W chunks = 2048 floats. Dual accumulators.
__device__ __forceinline__ float2 proj_run(
    const float* __restrict__ Ab, size_t As,
    const float* __restrict__ Wt, int nch,
    float* sAp, float* sWp, int tid, int rg, int c, int m0)
{
    u64 acc0 = 0ull, acc1 = 0ull;
    float rA[2];
    #pragma unroll
    for (int p = 0; p < 2; p++) rA[p] = Ab[(size_t)(m0 + rg + 8*p) * As + c];
    #pragma unroll
    for (int i = 0; i < 2; i++)
        cp16(sWp + (tid + i*256) * 4, Wt + (tid + i*256) * 4);
    cp_commit();
    #pragma unroll
    for (int p = 0; p < 2; p++) sAp[c * 34 + rg + 8*p] = rA[p];
    cp_wait0(); __syncthreads();

    for (int ch = 0; ch < nch; ch++) {
        const int cur = ch & 1, nxt = cur ^ 1;
        const bool more = (ch + 1 < nch);
        if (more) {
            const int k0 = (ch + 1) * 32;
            #pragma unroll
            for (int p = 0; p < 2; p++)
                rA[p] = Ab[(size_t)(m0 + rg + 8*p) * As + k0 + c];
            const float* wb = Wt + (size_t)(ch + 1) * 2048;
            #pragma unroll
            for (int i = 0; i < 2; i++)
                cp16(sWp + nxt * 6144 + (tid + i*256) * 4, wb + (tid + i*256) * 4);
            cp_commit();
        }
        const float* sAc = sAp + cur * (32 * 34);
        const float* sWc = sWp + cur * 6144;
        #pragma unroll
        for (int kk = 0; kk < 32; kk += 2) {
            u64 a0 = *(const u64*)&sAc[kk * 34 + rg * 2];
            u64 w0 = *(const u64*)&sWc[kk * 64 + 2 * c];
            ffma2(acc0, a0, w0);
            u64 a1 = *(const u64*)&sAc[(kk + 1) * 34 + rg * 2];
            u64 w1 = *(const u64*)&sWc[(kk + 1) * 64 + 2 * c];
            ffma2(acc1, a1, w1);
        }
        if (more) {
            float* sAn = sAp + nxt * (32 * 34);
            #pragma unroll
            for (int p = 0; p < 2; p++) sAn[c * 34 + rg + 8*p] = rA[p];
        }
        cp_wait0(); __syncthreads();
    }
    float2 x = unpack2(acc0), y = unpack2(acc1);
    return make_float2(x.x + y.x, x.y + y.y);
}

// 32m x 32j x 3seg gates GEMM, W chunks = 6144 floats.
__device__ __forceinline__ void gates_run(
    u64 (&acc)[3][2],
    const float* __restrict__ Ab, size_t As,
    const float* __restrict__ Wt, int nch,
    float* sAp, float* sWp, int tid, int rg, int c, int m0)
{
    float rA[4];
    #pragma unroll
    for (int p = 0; p < 4; p++) rA[p] = Ab[(size_t)(m0 + rg + 8*p) * As + c];
    #pragma unroll
    for (int i = 0; i < 6; i++)
        cp16(sWp + (tid + i*256) * 4, Wt + (tid + i*256) * 4);
    cp_commit();
    #pragma unroll
    for (int p = 0; p < 4; p++) sAp[c * 34 + rg + 8*p] = rA[p];
    cp_wait0(); __syncthreads();

    for (int ch = 0; ch < nch; ch++) {
        const int cur = ch & 1, nxt = cur ^ 1;
        const bool more = (ch + 1 < nch);
        if (more) {
            const int k0 = (ch + 1) * 32;
            #pragma unroll
            for (int p = 0; p < 4; p++)
                rA[p] = Ab[(size_t)(m0 + rg + 8*p) * As + k0 + c];
            const float* wb = Wt + (size_t)(ch + 1) * 6144;
            #pragma unroll
            for (int i = 0; i < 6; i++)
                cp16(sWp + nxt * 6144 + (tid + i*256) * 4, wb + (tid + i*256) * 4);
            cp_commit();
        }
        const float* sAc = sAp + cur * (32 * 34);
        const float* sWc = sWp + cur * 6144;
        #pragma unroll
        for (int kk = 0; kk < 32; kk++) {
            u64 a01 = *(const u64*)&sAc[kk * 34 + rg * 4];
            u64 a23 = *(const u64*)&sAc[kk * 34 + rg * 4 + 2];
            #pragma unroll
            for (int s = 0; s < 3; s++) {
                u64 w = *(const u64*)&sWc[kk * 192 + s * 64 + 2 * c];
                ffma2(acc[s][0], a01, w);
                ffma2(acc[s][1], a23, w);
            }
        }
        if (more) {
            float* sAn = sAp + nxt * (32 * 34);
            #pragma unroll
            for (int p = 0; p < 4; p++) sAn[c * 34 + rg + 8*p] = rA[p];
        }
        cp_wait0(); __syncthreads();
    }
}

// ---------------------------------------------------------------------------
// Persistent per-level scan. 3 phases / 3 grid barriers per step.
// ---------------------------------------------------------------------------
__global__ __launch_bounds__(256, 1) void level_kernel(
    float* __restrict__ dets, int T,
    const float* __restrict__ pre_ctx, int T1,
    const float* __restrict__ pre_obs,
    const float* __restrict__ Wih_t, const float* __restrict__ Whh_t,
    const float* __restrict__ Wq_t,  const float* __restrict__ Wcomb_t,
    const float* __restrict__ bih, const float* __restrict__ bhh,
    const float* __restrict__ bq,  const float* __restrict__ bp)
{
    __shared__ __align__(16) float sA[2][32][34];
    __shared__ __align__(16) float sW[2][6144];

    const int tid = threadIdx.x;
    const int bid = blockIdx.x;
    const int rg  = tid >> 5;      // warp 0..7
    const int c   = tid & 31;      // lane
    const size_t ldd = (size_t)T * DETER;

    const int m0g = (bid & 3) * 32;   // P2: 32m x 32j
    const int jt  = bid >> 2;
    const int j0  = jt * 32;
    const int m0s = (bid & 7) * 16;   // P1/P3: 16m x 32n
    const int nt  = bid >> 3;
    const int n0  = nt * 32;
    const int n   = n0 + c;

    float* sAp = &sA[0][0][0];
    float* sWp = &sW[0][0];

    // loop-invariant bias combos
    const int   j    = j0 + c;
    const float br   = bih[j] + bhh[j];
    const float bz   = bih[DETER + j] + bhh[DETER + j];
    const float bin_ = bih[2 * DETER + j];
    const float bhn  = bhh[2 * DETER + j];
    const float bb_bp = bp[n];
    const float bb_bv = g_bvec[n];
    const float bb_bq = bq[n];

    const float* Wcomb_b = Wcomb_t + (size_t)nt * 16 * 2048;
    const float* Wq_b    = Wq_t    + (size_t)nt * 32 * 2048;
    const float* Wih_b   = Wih_t   + (size_t)jt * 16 * 6144;
    const float* Whh_b   = Whh_t   + (size_t)jt * 32 * 6144;

    for (int t = 0; t < T; t++) {
        // ======================= P1: h =====================================
        {
            const int mA = m0s + rg * 2, mB = mA + 1;
            float pc0 = 0.f, pc1 = 0.f;
            if (pre_ctx) {
                const int tt = t & (T1 - 1);
                pc0 = pre_ctx[((size_t)mA * T1 + tt) * EMBED + n];
                pc1 = pre_ctx[((size_t)mB * T1 + tt) * EMBED + n];
            }
            float v0 = 0.f, v1 = 0.f;
            if (t > 0) {
                float2 s = proj_run(g_qh, EMBED, Wcomb_b, 16,
                                    sAp, sWp, tid, rg, c, m0s);
                v0 = s.x; v1 = s.y;
            }
            const float bb = (t == 0) ? bb_bp : bb_bv;
            g_h[mA * EMBED + n] = fmaxf(v0 + bb + pc0, 0.f);
            g_h[mB * EMBED + n] = fmaxf(v1 + bb + pc1, 0.f);
        }
        grid_sync();

        // ============ P2: gates (gi & gh) + GRU combine =====================
        {
            u64 ai[3][2] = {{0ull,0ull},{0ull,0ull},{0ull,0ull}};
            u64 ah[3][2] = {{0ull,0ull},{0ull,0ull},{0ull,0ull}};

            const float* dold = dets + (size_t)(t - 1) * DETER;
            float dold_r[4] = {0.f, 0.f, 0.f, 0.f};
            if (t > 0) {
                #pragma unroll
                for (int i = 0; i < 4; i++)
                    dold_r[i] = dold[(size_t)(m0g + rg * 4 + i) * ldd + j];
            }

            gates_run(ai, g_h, EMBED, Wih_b, 16, sAp, sWp, tid, rg, c, m0g);
            if (t > 0)
                gates_run(ah, dold, ldd, Whh_b, 32, sAp, sWp, tid, rg, c, m0g);

            float* dnew = dets + (size_t)t * DETER;
            #pragma unroll
            for (int pr = 0; pr < 2; pr++) {
                float2 vr = unpack2(ai[0][pr]); float2 hr = unpack2(ah[0][pr]);
                float2 vz = unpack2(ai[1][pr]); float2 hz = unpack2(ah[1][pr]);
                float2 vn = unpack2(ai[2][pr]); float2 hn = unpack2(ah[2][pr]);
                #pragma unroll
                for (int q = 0; q < 2; q++) {
                    const int i = pr * 2 + q;
                    const int m = m0g + rg * 4 + i;
                    float gr  = (q ? vr.y + hr.y : vr.x + hr.x) + br;
                    float gz  = (q ? vz.y + hz.y : vz.x + hz.x) + bz;
                    float inn = (q ? vn.y : vn.x) + bin_;
                    float hnn = (q ? hn.y : hn.x) + bhn;
                    float rr = 1.f / (1.f + expf(-gr));
                    float zz = 1.f / (1.f + expf(-gz));
                    float nn = tanhf(inn + rr * hnn);
                    dnew[(size_t)m * ldd + j] = (1.f - zz) * nn + zz * dold_r[i];
                }
            }
        }
        grid_sync();

        // ======================= P3: qh ====================================
        {
            const float* dnew = dets + (size_t)t * DETER;
            const int mA = m0s + rg * 2, mB = mA + 1;
            const float po0 = pre_obs[((size_t)mA * T + t) * EMBED + n];
            const float po1 = pre_obs[((size_t)mB * T + t) * EMBED + n];
            float2 s = proj_run(dnew, ldd, Wq_b, 32,
                                sAp, sWp, tid, rg, c, m0s);
            g_qh[mA * EMBED + n] = fmaxf(s.x + bb_bq + po0, 0.f);
            g_qh[mB * EMBED + n] = fmaxf(s.y + bb_bq + po1, 0.f);
        }
        grid_sync();
    }
}

// ---------------------------------------------------------------------------
// Host driver
// ---------------------------------------------------------------------------
extern "C" void kernel_launch(void* const* d_in, const int* in_sizes, int n_in,
                              void* d_out, int out_size)
{
    (void)in_sizes; (void)n_in; (void)out_size;
    const float* obs_arr[3] = {
        (const float*)d_in[0], (const float*)d_in[1], (const float*)d_in[2] };
    const float* Wp  = (const float*)d_in[3];
    const float* bp  = (const float*)d_in[4];
    const float* Wih = (const float*)d_in[5];
    const float* Whh = (const float*)d_in[6];
    const float* bih = (const float*)d_in[7];
    const float* bhh = (const float*)d_in[8];
    const float* Wq  = (const float*)d_in[9];
    const float* bq  = (const float*)d_in[10];
    const float* Wqm = (const float*)d_in[11];
    const float* bqm = (const float*)d_in[12];

    float *d1_, *d2_, *pc_, *po_, *wc_;
    float *wih_t, *whh_t, *wq_t, *wcomb_t;
    cudaGetSymbolAddress((void**)&d1_, g_dets1);
    cudaGetSymbolAddress((void**)&d2_, g_dets2);
    cudaGetSymbolAddress((void**)&pc_, g_pre_ctx);
    cudaGetSymbolAddress((void**)&po_, g_pre_obs);
    cudaGetSymbolAddress((void**)&wc_, g_Wcomb);
    cudaGetSymbolAddress((void**)&wih_t, g_Wih_t);
    cudaGetSymbolAddress((void**)&whh_t, g_Whh_t);
    cudaGetSymbolAddress((void**)&wq_t,  g_Wq_t);
    cudaGetSymbolAddress((void**)&wcomb_t, g_Wcomb_t);

    const int Ts[3] = { T0, T0 / 4, T0 / 16 };   // 256, 64, 16
    float* dets[3]  = { (float*)d_out, d1_, d2_ };

    for (int level = LVL - 1; level >= 0; level--) {
        const int T = Ts[level];
        const float* Wp_l  = Wp  + (size_t)level * (STOCH + DETER) * EMBED;
        const float* bp_l  = bp  + (size_t)level * EMBED;
        const float* Wih_l = Wih + (size_t)level * EMBED * G3;
        const float* Whh_l = Whh + (size_t)level * DETER * G3;
        const float* bih_l = bih + (size_t)level * G3;
        const float* bhh_l = bhh + (size_t)level * G3;
        const float* Wq_l  = Wq  + (size_t)level * (DETER + OBS_D) * EMBED;
        const float* bq_l  = bq  + (size_t)level * EMBED;
        const float* Wqm_l = Wqm + (size_t)level * EMBED * STOCH;
        const float* bqm_l = bqm + (size_t)level * STOCH;

        // Wcomb = Wqm @ Wp_sample   (512x512, K=128)
        {
            dim3 g(EMBED / 64, EMBED / 64);
            gemm64_kernel<<<g, 128>>>(Wqm_l, STOCH, Wp_l, EMBED,
                                      wc_, EMBED, STOCH);
        }
        // bvec = bp + bqm @ Wp_sample
        bvec_kernel<<<2, 256>>>(Wp_l, bp_l, bqm_l);

        // dup + tile the scan weights
        dup_tile_kernel<<<2048, 256>>>(Wih_l, wih_t, 512,  3, 1024);
        dup_tile_kernel<<<2048, 256>>>(Whh_l, whh_t, 1024, 3, 1024);
        dup_tile_kernel<<<1024, 256>>>(Wq_l,  wq_t,  1024, 1, 512);
        dup_tile_kernel<<<1024, 256>>>(wc_,   wcomb_t, 512, 1, 512);

        const float* pre_ctx = nullptr;
        int T1 = 1;
        if (level < LVL - 1) {
            T1 = Ts[level + 1];
            dim3 g(EMBED / 64, (BSZ * T1) / 64);
            gemm64_kernel<<<g, 128>>>(
                dets[level + 1], DETER,
                Wp_l + (size_t)STOCH * EMBED, EMBED,
                pc_, EMBED, DETER);
            pre_ctx = pc_;
        }

        // pre_obs = obs @ Wq_obs  (K=512)
        {
            dim3 g(EMBED / 64, (BSZ * T) / 64);
            gemm64_kernel<<<g, 128>>>(
                obs_arr[level], OBS_D,
                Wq_l + (size_t)DETER * EMBED, EMBED,
                po_, EMBED, OBS_D);
        }

        level_kernel<<<NB, 256>>>(
            dets[level], T, pre_ctx, T1, po_,
            wih_t, whh_t, wq_t, wcomb_t,
            bih_l, bhh_l, bq_l, bp_l);
    }
}

// round 11
// speedup vs baseline: 1.0878x; 1.0878x over previous
#include <cuda_runtime.h>
#include <cstdint>
#include <cstddef>
#include <math.h>

#define LVL   3
#define BSZ   128
#define T0    256
#define STOCH 128
#define DETER 1024
#define EMBED 512
#define OBS_D 512
#define G3    (3*DETER)   // 3072
#define NB    128          // persistent grid (<=148 SMs, all co-resident)

typedef unsigned long long u64;

// ---------------------------------------------------------------------------
// Static device scratch (no allocations allowed).
// Transposed activations: X_T[k][m] (m contiguous, 128 floats per row).
// ---------------------------------------------------------------------------
__device__ __align__(16) float g_hT [EMBED * BSZ];
__device__ __align__(16) float g_qhT[EMBED * BSZ];
__device__ __align__(16) float g_detT[2][DETER * BSZ];   // ping-pong by t&1
__device__ float g_dets1[BSZ * 64 * DETER];     // level-1 dets (std layout)
__device__ float g_dets2[BSZ * 16 * DETER];     // level-2 dets (std layout)
__device__ float g_pre_ctx[BSZ * 64 * EMBED];   // ctx @ Wp_ctx
__device__ float g_pre_obs[BSZ * T0 * EMBED];   // obs @ Wq_obs
__device__ float g_Wcomb[EMBED * EMBED];        // Wqm @ Wp_sample (std layout)
__device__ float g_bvec[EMBED];                 // bp + bqm @ Wp_sample
// Duplicated {w,w} pairs, chunk-tiled in exact smem-consumption order.
__device__ __align__(16) float g_Wih_d[EMBED * G3 * 2];     // 12.6 MB
__device__ __align__(16) float g_Whh_d[DETER * G3 * 2];     // 25.2 MB
__device__ __align__(16) float g_Wq_d [DETER * EMBED * 2];  //  4.2 MB
__device__ __align__(16) float g_Wc_d [EMBED * EMBED * 2];  //  2.1 MB
__device__ unsigned int g_bar_count;
__device__ unsigned int g_bar_gen;

// ---------------------------------------------------------------------------
// Packed fp32 FMA (bit-exact fp32) + cp.async helpers
// ---------------------------------------------------------------------------
__device__ __forceinline__ void ffma2(u64& d, u64 a, u64 b) {
    asm("fma.rn.f32x2 %0, %1, %2, %0;" : "+l"(d) : "l"(a), "l"(b));
}
__device__ __forceinline__ float2 unpack2(u64 v) {
    float lo, hi;
    asm("mov.b64 {%0, %1}, %2;" : "=f"(lo), "=f"(hi) : "l"(v));
    return make_float2(lo, hi);
}
__device__ __forceinline__ void cp16(float* s, const float* g) {
    unsigned a = (unsigned)__cvta_generic_to_shared(s);
    asm volatile("cp.async.cg.shared.global [%0], [%1], 16;" :: "r"(a), "l"(g));
}
__device__ __forceinline__ void cp_commit() { asm volatile("cp.async.commit_group;"); }
__device__ __forceinline__ void cp_wait0()  { asm volatile("cp.async.wait_group 0;"); }

// ---------------------------------------------------------------------------
// Software grid barrier. NB blocks all co-resident.
// ---------------------------------------------------------------------------
__device__ __forceinline__ void grid_sync() {
    __syncthreads();
    if (threadIdx.x == 0) {
        volatile unsigned int* genp = &g_bar_gen;
        unsigned int g = *genp;
        __threadfence();
        unsigned int a = atomicAdd(&g_bar_count, 1u);
        if (a == NB - 1u) {
            atomicExch(&g_bar_count, 0u);
            __threadfence();
            atomicAdd(&g_bar_gen, 1u);
        } else {
            while (*genp == g) { }
        }
        __threadfence();
    }
    __syncthreads();
}

// ---------------------------------------------------------------------------
// Precompute GEMM: C[M,N] = A[M,K] @ W[K,N]
// ---------------------------------------------------------------------------
__global__ __launch_bounds__(128) void gemm64_kernel(
    const float* __restrict__ A, int lda,
    const float* __restrict__ W, int ldw,
    float* __restrict__ C, int ldc, int K)
{
    constexpr int BM = 64, BN = 64, BK = 16, TM = 4, TN = 8;
    __shared__ float sA[BK][BM + 4];
    __shared__ float sW[BK][BN];

    const int tid  = threadIdx.x;
    const int tx   = tid & 7;
    const int ty   = tid >> 3;
    const int row0 = blockIdx.y * BM;
    const int col0 = blockIdx.x * BN;

    float acc[TM][TN];
    #pragma unroll
    for (int i = 0; i < TM; i++)
        #pragma unroll
        for (int j = 0; j < TN; j++) acc[i][j] = 0.0f;

    for (int k0 = 0; k0 < K; k0 += BK) {
        #pragma unroll
        for (int p = 0; p < 8; p++) {
            int i  = tid + p * 128;
            int kk = i & 15, r = i >> 4;
            sA[kk][r] = A[(size_t)(row0 + r) * lda + (k0 + kk)];
        }
        #pragma unroll
        for (int p = 0; p < 8; p++) {
            int i  = tid + p * 128;
            int kk = i >> 6, cc = i & 63;
            sW[kk][cc] = W[(size_t)(k0 + kk) * ldw + (col0 + cc)];
        }
        __syncthreads();
        #pragma unroll
        for (int kk = 0; kk < BK; kk++) {
            float4 av = *(const float4*)&sA[kk][ty * TM];
            float4 w0 = *(const float4*)&sW[kk][tx * TN];
            float4 w1 = *(const float4*)&sW[kk][tx * TN + 4];
            float a[TM] = {av.x, av.y, av.z, av.w};
            float w[TN] = {w0.x, w0.y, w0.z, w0.w, w1.x, w1.y, w1.z, w1.w};
            #pragma unroll
            for (int i = 0; i < TM; i++)
                #pragma unroll
                for (int j = 0; j < TN; j++)
                    acc[i][j] = fmaf(a[i], w[j], acc[i][j]);
        }
        __syncthreads();
    }

    #pragma unroll
    for (int i = 0; i < TM; i++) {
        int m  = row0 + ty * TM + i;
        int n0 = col0 + tx * TN;
        float4 o0 = {acc[i][0], acc[i][1], acc[i][2], acc[i][3]};
        float4 o1 = {acc[i][4], acc[i][5], acc[i][6], acc[i][7]};
        *(float4*)&C[(size_t)m * ldc + n0]     = o0;
        *(float4*)&C[(size_t)m * ldc + n0 + 4] = o1;
    }
}

// bvec[n] = bp[n] + sum_s bqm[s] * Wp_sample[s, n]
__global__ void bvec_kernel(const float* __restrict__ Wp,
                            const float* __restrict__ bp,
                            const float* __restrict__ bqm)
{
    const int n = blockIdx.x * blockDim.x + threadIdx.x;
    if (n >= EMBED) return;
    float s = bp[n];
    for (int k = 0; k < STOCH; k++)
        s = fmaf(bqm[k], Wp[(size_t)k * EMBED + n], s);
    g_bvec[n] = s;
}

// ---------------------------------------------------------------------------
// Dup+tile passes.
// Gates: pair o = ((jblk*nch + ch)*32 + kk)*24 + seg*8 + jl
//        value  = W[(ch*32+kk)][seg*1024 + jblk*8 + jl]; chunk = 1536 floats.
// Proj:  pair o = ((nblk*nch + ch)*32 + kk)*4 + nl
//        value  = W[(ch*32+kk)][nblk*4 + nl];             chunk = 256 floats.
// ---------------------------------------------------------------------------
__global__ void dup_gates_kernel(const float* __restrict__ src,
                                 float* __restrict__ dst, int K)
{
    const int nch = K / 32;
    const long total = (long)K * G3;
    for (long o = (long)blockIdx.x * blockDim.x + threadIdx.x; o < total;
         o += (long)gridDim.x * blockDim.x) {
        int jl  = (int)(o & 7);
        long r  = o >> 3;
        int seg = (int)(r % 3);  r /= 3;
        int kk  = (int)(r & 31); r >>= 5;
        int ch  = (int)(r % nch);
        int jblk = (int)(r / nch);
        float v = src[(size_t)(ch * 32 + kk) * G3 + seg * DETER + jblk * 8 + jl];
        *(float2*)&dst[o * 2] = make_float2(v, v);
    }
}

__global__ void dup_proj_kernel(const float* __restrict__ src,
                                float* __restrict__ dst, int K)
{
    const int nch = K / 32;
    const long total = (long)K * EMBED;
    for (long o = (long)blockIdx.x * blockDim.x + threadIdx.x; o < total;
         o += (long)gridDim.x * blockDim.x) {
        int nl  = (int)(o & 3);
        long r  = o >> 2;
        int kk  = (int)(r & 31); r >>= 5;
        int ch  = (int)(r % nch);
        int nblk = (int)(r / nch);
        float v = src[(size_t)(ch * 32 + kk) * EMBED + nblk * 4 + nl];
        *(float2*)&dst[o * 2] = make_float2(v, v);
    }
}

// ---------------------------------------------------------------------------
// Scan GEMM cores. sAp: 2 x 4096 floats ([kk][m], m contiguous).
// sWp: 2 x 1536 floats (gates) / first 256 used (proj).
// ---------------------------------------------------------------------------

// 2m x 1n projection accumulate over K = nch*32 (A transposed in gmem).
// Wb is the UNFOLDED 16B-aligned chunk base; the per-thread n offset (nloc2,
// in floats, 8B-aligned) is applied only at the smem read.
__device__ __forceinline__ u64 proj_accum(
    const float* __restrict__ AT, const float* __restrict__ Wb, int nch,
    float* sAp, float* sWp, int tid, int mb, int nloc2)
{
    u64 acc = 0ull;
    #pragma unroll
    for (int p = 0; p < 4; p++)
        cp16(sAp + (tid + p*256) * 4, AT + (tid + p*256) * 4);
    if (tid < 64) cp16(sWp + tid * 4, Wb + tid * 4);
    cp_commit(); cp_wait0(); __syncthreads();

    for (int ch = 0; ch < nch; ch++) {
        const int cur = ch & 1;
        const float* sAc = sAp + cur * 4096;
        const float* sWc = sWp + cur * 1536 + nloc2;
        if (ch + 1 < nch) {
            float* sAn = sAp + (cur ^ 1) * 4096;
            float* sWn = sWp + (cur ^ 1) * 1536;
            const float* a1 = AT + (size_t)(ch + 1) * 4096;
            const float* w1 = Wb + (size_t)(ch + 1) * 256;
            #pragma unroll
            for (int p = 0; p < 4; p++)
                cp16(sAn + (tid + p*256) * 4, a1 + (tid + p*256) * 4);
            if (tid < 64) cp16(sWn + tid * 4, w1 + tid * 4);
            cp_commit();
        }
        #pragma unroll
        for (int kk = 0; kk < 32; kk++) {
            u64 a = *(const u64*)(sAc + kk * 128 + mb);
            u64 w = *(const u64*)(sWc + kk * 8);
            ffma2(acc, a, w);
        }
        cp_wait0(); __syncthreads();
    }
    return acc;
}

// 4m x 1j x 3seg gates accumulate over K = nch*32.
__device__ __forceinline__ void gates_accum(
    u64* aR, u64* aZ, u64* aN,
    const float* __restrict__ AT, const float* __restrict__ Wb, int nch,
    float* sAp, float* sWp, int tid, int mb2, int jloc2)
{
    #pragma unroll
    for (int p = 0; p < 4; p++)
        cp16(sAp + (tid + p*256) * 4, AT + (tid + p*256) * 4);
    cp16(sWp + tid * 4, Wb + tid * 4);
    if (tid < 128) cp16(sWp + (tid + 256) * 4, Wb + (tid + 256) * 4);
    cp_commit(); cp_wait0(); __syncthreads();

    for (int ch = 0; ch < nch; ch++) {
        const int cur = ch & 1;
        const float* sAc = sAp + cur * 4096;
        const float* sWc = sWp + cur * 1536 + jloc2;
        if (ch + 1 < nch) {
            float* sAn = sAp + (cur ^ 1) * 4096;
            float* sWn = sWp + (cur ^ 1) * 1536;
            const float* a1 = AT + (size_t)(ch + 1) * 4096;
            const float* w1 = Wb + (size_t)(ch + 1) * 1536;
            #pragma unroll
            for (int p = 0; p < 4; p++)
                cp16(sAn + (tid + p*256) * 4, a1 + (tid + p*256) * 4);
            cp16(sWn + tid * 4, w1 + tid * 4);
            if (tid < 128) cp16(sWn + (tid + 256) * 4, w1 + (tid + 256) * 4);
            cp_commit();
        }
        #pragma unroll
        for (int kk = 0; kk < 32; kk++) {
            ulonglong2 a = *(const ulonglong2*)(sAc + kk * 128 + mb2);
            u64 w0 = *(const u64*)(sWc + kk * 48);
            u64 w1 = *(const u64*)(sWc + kk * 48 + 16);
            u64 w2 = *(const u64*)(sWc + kk * 48 + 32);
            ffma2(aR[0], a.x, w0); ffma2(aR[1], a.y, w0);
            ffma2(aZ[0], a.x, w1); ffma2(aZ[1], a.y, w1);
            ffma2(aN[0], a.x, w2); ffma2(aN[1], a.y, w2);
        }
        cp_wait0(); __syncthreads();
    }
}

// ---------------------------------------------------------------------------
// Persistent per-level scan. 3 phases / 3 grid barriers per step.
//   P1: h_T  = relu(qh @ Wcomb + bvec + pre_ctx)     (t=0: relu(bp + pre_ctx))
//   P2: gates + GRU -> detT_new (ping-pong) + dets (std layout / d_out)
//   P3: qh_T = relu(det_new @ Wq_det + bq + pre_obs)
// ---------------------------------------------------------------------------
__global__ __launch_bounds__(256, 1) void level_kernel(
    float* __restrict__ dets, int T,
    const float* __restrict__ pre_ctx, int T1,
    const float* __restrict__ pre_obs,
    const float* __restrict__ bih, const float* __restrict__ bhh,
    const float* __restrict__ bq,  const float* __restrict__ bp)
{
    __shared__ __align__(16) float sA[2 * 4096];
    __shared__ __align__(16) float sW[2 * 1536];

    const int tid  = threadIdx.x;
    const int bid  = blockIdx.x;
    const int rg   = tid >> 5;
    const int lane = tid & 31;
    const size_t ldd = (size_t)T * DETER;

    // P2 coords: lanes = 8 m-lanes x 4 j-lanes; warps = 4 m-groups x 2 j-groups
    const int mb2   = (rg & 3) * 32 + (lane & 7) * 4;   // 4 m per thread
    const int jloc  = (rg >> 2) * 4 + (lane >> 3);      // 0..7
    const int jloc2 = jloc * 2;
    const int j     = bid * 8 + jloc;

    // P1/P3 coords: lanes = 16 m-lanes x 2 n-lanes; warps = 4 m-groups x 2 n-groups
    const int mb   = (rg & 3) * 32 + (lane & 15) * 2;   // 2 m per thread
    const int nloc = (rg >> 2) * 2 + (lane >> 4);       // 0..3
    const int nloc2 = nloc * 2;
    const int n    = bid * 4 + nloc;

    // loop invariants
    const float br   = bih[j] + bhh[j];
    const float bz   = bih[DETER + j] + bhh[DETER + j];
    const float bin_ = bih[2 * DETER + j];
    const float bhn  = bhh[2 * DETER + j];
    const float bp_n = bp[n];
    const float bv_n = g_bvec[n];
    const float bq_n = bq[n];

    const float* Wih_b = g_Wih_d + (size_t)bid * 16 * 1536;
    const float* Whh_b = g_Whh_d + (size_t)bid * 32 * 1536;
    const float* Wq_b  = g_Wq_d  + (size_t)bid * 32 * 256;   // unfolded, 16B-aligned
    const float* Wc_b  = g_Wc_d  + (size_t)bid * 16 * 256;   // unfolded, 16B-aligned

    for (int t = 0; t < T; t++) {
        float* detT_new = g_detT[t & 1];
        const float* detT_old = g_detT[(t & 1) ^ 1];

        // ======================= P1: h_T ===================================
        {
            float pc0 = 0.f, pc1 = 0.f;
            if (pre_ctx) {
                const int tt = t & (T1 - 1);
                pc0 = pre_ctx[((size_t)mb * T1 + tt) * EMBED + n];
                pc1 = pre_ctx[((size_t)(mb + 1) * T1 + tt) * EMBED + n];
            }
            float2 v = make_float2(0.f, 0.f);
            if (t > 0)
                v = unpack2(proj_accum(g_qhT, Wc_b, 16, sA, sW, tid, mb, nloc2));
            const float bb = (t == 0) ? bp_n : bv_n;
            float2 o = make_float2(fmaxf(v.x + bb + pc0, 0.f),
                                   fmaxf(v.y + bb + pc1, 0.f));
            *(float2*)&g_hT[n * 128 + mb] = o;
        }
        grid_sync();

        // ============ P2: gates (gi & gh) + GRU combine ====================
        {
            u64 aR[2] = {0ull, 0ull}, aZ[2] = {0ull, 0ull};
            u64 aNi[2] = {0ull, 0ull}, aNh[2] = {0ull, 0ull};

            float4 dold4 = make_float4(0.f, 0.f, 0.f, 0.f);
            if (t > 0)
                dold4 = *(const float4*)&detT_old[j * 128 + mb2];

            gates_accum(aR, aZ, aNi, g_hT, Wih_b, 16, sA, sW, tid, mb2, jloc2);
            if (t > 0)
                gates_accum(aR, aZ, aNh, detT_old, Whh_b, 32, sA, sW, tid, mb2, jloc2);

            float R[4], Z[4], Ni[4], Nh[4], D[4], dn[4];
            { float2 x = unpack2(aR[0]), y = unpack2(aR[1]);
              R[0]=x.x; R[1]=x.y; R[2]=y.x; R[3]=y.y; }
            { float2 x = unpack2(aZ[0]), y = unpack2(aZ[1]);
              Z[0]=x.x; Z[1]=x.y; Z[2]=y.x; Z[3]=y.y; }
            { float2 x = unpack2(aNi[0]), y = unpack2(aNi[1]);
              Ni[0]=x.x; Ni[1]=x.y; Ni[2]=y.x; Ni[3]=y.y; }
            { float2 x = unpack2(aNh[0]), y = unpack2(aNh[1]);
              Nh[0]=x.x; Nh[1]=x.y; Nh[2]=y.x; Nh[3]=y.y; }
            D[0]=dold4.x; D[1]=dold4.y; D[2]=dold4.z; D[3]=dold4.w;

            #pragma unroll
            for (int i = 0; i < 4; i++) {
                float rr = 1.f / (1.f + expf(-(R[i] + br)));
                float zz = 1.f / (1.f + expf(-(Z[i] + bz)));
                float hnn = (t > 0) ? (Nh[i] + bhn) : bhn;
                float nn = tanhf(Ni[i] + bin_ + rr * hnn);
                dn[i] = (1.f - zz) * nn + zz * D[i];
            }
            *(float4*)&detT_new[j * 128 + mb2] =
                make_float4(dn[0], dn[1], dn[2], dn[3]);
            #pragma unroll
            for (int i = 0; i < 4; i++)
                dets[(size_t)(mb2 + i) * ldd + (size_t)t * DETER + j] = dn[i];
        }
        grid_sync();

        // ======================= P3: qh_T ==================================
        {
            const float po0 = pre_obs[((size_t)mb * T + t) * EMBED + n];
            const float po1 = pre_obs[((size_t)(mb + 1) * T + t) * EMBED + n];
            float2 v = unpack2(proj_accum(detT_new, Wq_b, 32, sA, sW, tid, mb, nloc2));
            float2 o = make_float2(fmaxf(v.x + bq_n + po0, 0.f),
                                   fmaxf(v.y + bq_n + po1, 0.f));
            *(float2*)&g_qhT[n * 128 + mb] = o;
        }
        grid_sync();
    }
}

// ---------------------------------------------------------------------------
// Host driver
// ---------------------------------------------------------------------------
extern "C" void kernel_launch(void* const* d_in, const int* in_sizes, int n_in,
                              void* d_out, int out_size)
{
    (void)in_sizes; (void)n_in; (void)out_size;
    const float* obs_arr[3] = {
        (const float*)d_in[0], (const float*)d_in[1], (const float*)d_in[2] };
    const float* Wp  = (const float*)d_in[3];
    const float* bp  = (const float*)d_in[4];
    const float* Wih = (const float*)d_in[5];
    const float* Whh = (const float*)d_in[6];
    const float* bih = (const float*)d_in[7];
    const float* bhh = (const float*)d_in[8];
    const float* Wq  = (const float*)d_in[9];
    const float* bq  = (const float*)d_in[10];
    const float* Wqm = (const float*)d_in[11];
    const float* bqm = (const float*)d_in[12];

    float *d1_, *d2_, *pc_, *po_, *wc_;
    float *wih_d, *whh_d, *wq_d, *wc_d;
    cudaGetSymbolAddress((void**)&d1_, g_dets1);
    cudaGetSymbolAddress((void**)&d2_, g_dets2);
    cudaGetSymbolAddress((void**)&pc_, g_pre_ctx);
    cudaGetSymbolAddress((void**)&po_, g_pre_obs);
    cudaGetSymbolAddress((void**)&wc_, g_Wcomb);
    cudaGetSymbolAddress((void**)&wih_d, g_Wih_d);
    cudaGetSymbolAddress((void**)&whh_d, g_Whh_d);
    cudaGetSymbolAddress((void**)&wq_d,  g_Wq_d);
    cudaGetSymbolAddress((void**)&wc_d,  g_Wc_d);

    const int Ts[3] = { T0, T0 / 4, T0 / 16 };   // 256, 64, 16
    float* dets[3]  = { (float*)d_out, d1_, d2_ };

    for (int level = LVL - 1; level >= 0; level--) {
        const int T = Ts[level];
        const float* Wp_l  = Wp  + (size_t)level * (STOCH + DETER) * EMBED;
        const float* bp_l  = bp  + (size_t)level * EMBED;
        const float* Wih_l = Wih + (size_t)level * EMBED * G3;
        const float* Whh_l = Whh + (size_t)level * DETER * G3;
        const float* bih_l = bih + (size_t)level * G3;
        const float* bhh_l = bhh + (size_t)level * G3;
        const float* Wq_l  = Wq  + (size_t)level * (DETER + OBS_D) * EMBED;
        const float* bq_l  = bq  + (size_t)level * EMBED;
        const float* Wqm_l = Wqm + (size_t)level * EMBED * STOCH;
        const float* bqm_l = bqm + (size_t)level * STOCH;

        // Wcomb = Wqm @ Wp_sample   (512x512, K=128)
        {
            dim3 g(EMBED / 64, EMBED / 64);
            gemm64_kernel<<<g, 128>>>(Wqm_l, STOCH, Wp_l, EMBED,
                                      wc_, EMBED, STOCH);
        }
        bvec_kernel<<<2, 256>>>(Wp_l, bp_l, bqm_l);

        // dup + tile scan weights into smem-image layout
        dup_gates_kernel<<<2048, 256>>>(Wih_l, wih_d, EMBED);
        dup_gates_kernel<<<2048, 256>>>(Whh_l, whh_d, DETER);
        dup_proj_kernel<<<1024, 256>>>(Wq_l, wq_d, DETER);
        dup_proj_kernel<<<1024, 256>>>(wc_,  wc_d, EMBED);

        const float* pre_ctx = nullptr;
        int T1 = 1;
        if (level < LVL - 1) {
            T1 = Ts[level + 1];
            dim3 g(EMBED / 64, (BSZ * T1) / 64);
            gemm64_kernel<<<g, 128>>>(
                dets[level + 1], DETER,
                Wp_l + (size_t)STOCH * EMBED, EMBED,
                pc_, EMBED, DETER);
            pre_ctx = pc_;
        }

        // pre_obs = obs @ Wq_obs  (K=512)
        {
            dim3 g(EMBED / 64, (BSZ * T) / 64);
            gemm64_kernel<<<g, 128>>>(
                obs_arr[level], OBS_D,
                Wq_l + (size_t)DETER * EMBED, EMBED,
                po_, EMBED, OBS_D);
        }

        level_kernel<<<NB, 256>>>(
            dets[level], T, pre_ctx, T1, po_,
            bih_l, bhh_l, bq_l, bp_l);
    }
}